// round 2
// baseline (speedup 1.0000x reference)
#include <cuda_runtime.h>

#define SEQ   2048
#define BATCH 2
#define DM    1024
#define NH    16
#define MTOT  (BATCH*SEQ)   // 4096

// Scratch (static device globals; allocation-guard safe)
__device__ float g_Qb[MTOT * DM];
__device__ float g_Kb[MTOT * DM];
__device__ float g_Vb[MTOT * DM];
__device__ float g_Ctx[MTOT * DM];

// ---------------------------------------------------------------------------
// SGEMM tile: C[m0:m0+128, n0:n0+128] = A[M,1024] @ W[1024,128-slice] * scale (+bias)
// 256 threads, BK=16, 8x8 micro-tile in split-register layout.
// ---------------------------------------------------------------------------
__device__ __forceinline__ void gemm_tile(
    const float* __restrict__ A, const float* __restrict__ W,
    float* __restrict__ C, const float* __restrict__ bias, float scale,
    int m0, int n0, float (&As)[16][132], float (&Bs)[16][128])
{
    const int tid = threadIdx.x;
    const int tx  = tid & 15;
    const int ty  = tid >> 4;

    float acc[8][8];
#pragma unroll
    for (int i = 0; i < 8; i++)
#pragma unroll
        for (int j = 0; j < 8; j++) acc[i][j] = 0.f;

    for (int k0 = 0; k0 < DM; k0 += 16) {
        // A tile: 128 rows x 16 k, stored transposed As[k][m]
#pragma unroll
        for (int e = 0; e < 2; e++) {
            int lin = tid + 256 * e;          // 0..511
            int m   = lin >> 2;
            int k4  = lin & 3;
            float4 v = *(const float4*)(A + (size_t)(m0 + m) * DM + k0 + k4 * 4);
            As[k4 * 4 + 0][m] = v.x;
            As[k4 * 4 + 1][m] = v.y;
            As[k4 * 4 + 2][m] = v.z;
            As[k4 * 4 + 3][m] = v.w;
        }
        // B tile: 16 k x 128 n, natural layout
#pragma unroll
        for (int e = 0; e < 2; e++) {
            int lin = tid + 256 * e;          // 0..511
            int k   = lin >> 5;
            int n4  = lin & 31;
            *(float4*)&Bs[k][n4 * 4] =
                *(const float4*)(W + (size_t)(k0 + k) * DM + n0 + n4 * 4);
        }
        __syncthreads();

#pragma unroll
        for (int kk = 0; kk < 16; kk++) {
            float a[8], b[8];
            *(float4*)&a[0] = *(const float4*)&As[kk][ty * 4];
            *(float4*)&a[4] = *(const float4*)&As[kk][64 + ty * 4];
            *(float4*)&b[0] = *(const float4*)&Bs[kk][tx * 4];
            *(float4*)&b[4] = *(const float4*)&Bs[kk][64 + tx * 4];
#pragma unroll
            for (int i = 0; i < 8; i++)
#pragma unroll
                for (int j = 0; j < 8; j++) acc[i][j] += a[i] * b[j];
        }
        __syncthreads();
    }

#pragma unroll
    for (int i = 0; i < 8; i++) {
        int r = m0 + ((i < 4) ? (ty * 4 + i) : (64 + ty * 4 + (i - 4)));
#pragma unroll
        for (int jh = 0; jh < 2; jh++) {
            int c = n0 + jh * 64 + tx * 4;
            float4 v;
            v.x = acc[i][jh * 4 + 0] * scale;
            v.y = acc[i][jh * 4 + 1] * scale;
            v.z = acc[i][jh * 4 + 2] * scale;
            v.w = acc[i][jh * 4 + 3] * scale;
            if (bias) {
                v.x += bias[c + 0]; v.y += bias[c + 1];
                v.z += bias[c + 2]; v.w += bias[c + 3];
            }
            *(float4*)(C + (size_t)r * DM + c) = v;
        }
    }
}

// QKV projection: z=0 -> Q (scaled by 1/sqrt(64)), z=1 -> K, z=2 -> V
__global__ __launch_bounds__(256, 2)
void proj_qkv_kernel(const float* __restrict__ X, const float* __restrict__ Wq,
                     const float* __restrict__ Wk, const float* __restrict__ Wv)
{
    __shared__ float As[16][132];
    __shared__ float Bs[16][128];
    const float* W; float* C; float scale;
    if (blockIdx.z == 0)      { W = Wq; C = g_Qb; scale = 0.125f; }
    else if (blockIdx.z == 1) { W = Wk; C = g_Kb; scale = 1.0f;  }
    else                      { W = Wv; C = g_Vb; scale = 1.0f;  }
    gemm_tile(X, W, C, nullptr, scale, blockIdx.y * 128, blockIdx.x * 128, As, Bs);
}

// Output projection with bias -> d_out
__global__ __launch_bounds__(256, 2)
void out_proj_kernel(const float* __restrict__ Wo, const float* __restrict__ bo,
                     float* __restrict__ Y)
{
    __shared__ float As[16][132];
    __shared__ float Bs[16][128];
    gemm_tile(g_Ctx, Wo, Y, bo, 1.0f, blockIdx.y * 128, blockIdx.x * 128, As, Bs);
}

// ---------------------------------------------------------------------------
// Flash-style attention, fp32. One block = one (b,h) pair x 64 queries.
// Bk = 32 keys per iteration, online softmax. 256 threads (tx 0..15, ty 0..15).
// Thread owns: S rows 4ty..4ty+3 x cols 2tx..2tx+1; O rows 4ty.. x dcols 4tx..
// ---------------------------------------------------------------------------
__global__ __launch_bounds__(256, 2)
void attn_kernel()
{
    __shared__ float Qt[64][65];   // [d][q], odd stride -> conflict-free scalar
    __shared__ float Kt[64][33];   // [d][k]
    __shared__ float Vs[32][64];   // [k][d], natural, float4-aligned
    __shared__ float Pt[32][68];   // [k][q], stride 68 = 16B aligned for float4 reads

    const int bh = blockIdx.x;            // 0..31
    const int b  = bh >> 4;
    const int h  = bh & 15;
    const int q0 = blockIdx.y * 64;
    const int tid = threadIdx.x;
    const int tx  = tid & 15;
    const int ty  = tid >> 4;

    const float* Qbase = g_Qb + ((size_t)(b * SEQ + q0)) * DM + h * 64;
    const float* Kbase = g_Kb + ((size_t)(b * SEQ)) * DM + h * 64;
    const float* Vbase = g_Vb + ((size_t)(b * SEQ)) * DM + h * 64;

    // Load Q tile transposed: 64 q-rows x 64 d
#pragma unroll
    for (int e = 0; e < 4; e++) {
        int lin = tid + 256 * e;          // 0..1023
        int qq  = lin >> 4;
        int d4  = lin & 15;
        float4 v = *(const float4*)(Qbase + (size_t)qq * DM + d4 * 4);
        Qt[d4 * 4 + 0][qq] = v.x;
        Qt[d4 * 4 + 1][qq] = v.y;
        Qt[d4 * 4 + 2][qq] = v.z;
        Qt[d4 * 4 + 3][qq] = v.w;
    }

    float m_[4], l_[4], o[4][4];
#pragma unroll
    for (int i = 0; i < 4; i++) {
        m_[i] = -1e30f;
        l_[i] = 0.f;
#pragma unroll
        for (int j = 0; j < 4; j++) o[i][j] = 0.f;
    }

    for (int kt = 0; kt < SEQ / 32; kt++) {
        __syncthreads();   // previous PV done before overwriting K/V tiles
        // Load K (transposed) and V (natural) tiles: 32 rows x 64 d each
#pragma unroll
        for (int e = 0; e < 2; e++) {
            int lin = tid + 256 * e;      // 0..511
            int kk  = lin >> 4;
            int d4  = lin & 15;
            float4 v = *(const float4*)(Kbase + (size_t)(kt * 32 + kk) * DM + d4 * 4);
            Kt[d4 * 4 + 0][kk] = v.x;
            Kt[d4 * 4 + 1][kk] = v.y;
            Kt[d4 * 4 + 2][kk] = v.z;
            Kt[d4 * 4 + 3][kk] = v.w;
            float4 w = *(const float4*)(Vbase + (size_t)(kt * 32 + kk) * DM + d4 * 4);
            *(float4*)&Vs[kk][d4 * 4] = w;
        }
        __syncthreads();

        // S = Q K^T  (scale already folded into Q at projection)
        float s[4][2];
#pragma unroll
        for (int i = 0; i < 4; i++) { s[i][0] = 0.f; s[i][1] = 0.f; }
#pragma unroll 16
        for (int d = 0; d < 64; d++) {
            float a0 = Qt[d][ty * 4 + 0];
            float a1 = Qt[d][ty * 4 + 1];
            float a2 = Qt[d][ty * 4 + 2];
            float a3 = Qt[d][ty * 4 + 3];
            float b0 = Kt[d][tx * 2 + 0];
            float b1 = Kt[d][tx * 2 + 1];
            s[0][0] += a0 * b0; s[0][1] += a0 * b1;
            s[1][0] += a1 * b0; s[1][1] += a1 * b1;
            s[2][0] += a2 * b0; s[2][1] += a2 * b1;
            s[3][0] += a3 * b0; s[3][1] += a3 * b1;
        }

        // Online softmax update (row reductions across the 16 tx lanes)
#pragma unroll
        for (int i = 0; i < 4; i++) {
            float mx = fmaxf(s[i][0], s[i][1]);
#pragma unroll
            for (int off = 1; off < 16; off <<= 1)
                mx = fmaxf(mx, __shfl_xor_sync(0xffffffffu, mx, off));
            float nm   = fmaxf(m_[i], mx);
            float corr = __expf(m_[i] - nm);
            float p0   = __expf(s[i][0] - nm);
            float p1   = __expf(s[i][1] - nm);
            float rs   = p0 + p1;
#pragma unroll
            for (int off = 1; off < 16; off <<= 1)
                rs += __shfl_xor_sync(0xffffffffu, rs, off);
            l_[i] = l_[i] * corr + rs;
            m_[i] = nm;
#pragma unroll
            for (int j = 0; j < 4; j++) o[i][j] *= corr;
            Pt[tx * 2 + 0][ty * 4 + i] = p0;
            Pt[tx * 2 + 1][ty * 4 + i] = p1;
        }
        __syncthreads();

        // O += P @ V
#pragma unroll 8
        for (int kk = 0; kk < 32; kk++) {
            float4 a  = *(const float4*)&Pt[kk][ty * 4];
            float4 bb = *(const float4*)&Vs[kk][tx * 4];
            o[0][0] += a.x * bb.x; o[0][1] += a.x * bb.y; o[0][2] += a.x * bb.z; o[0][3] += a.x * bb.w;
            o[1][0] += a.y * bb.x; o[1][1] += a.y * bb.y; o[1][2] += a.y * bb.z; o[1][3] += a.y * bb.w;
            o[2][0] += a.z * bb.x; o[2][1] += a.z * bb.y; o[2][2] += a.z * bb.z; o[2][3] += a.z * bb.w;
            o[3][0] += a.w * bb.x; o[3][1] += a.w * bb.y; o[3][2] += a.w * bb.z; o[3][3] += a.w * bb.w;
        }
    }

    // Normalize and write ctx in [bs, h*64+d] layout (ready for out projection)
    float* Obase = g_Ctx + ((size_t)(b * SEQ + q0)) * DM + h * 64;
#pragma unroll
    for (int i = 0; i < 4; i++) {
        float inv = 1.0f / l_[i];
        float4 v;
        v.x = o[i][0] * inv; v.y = o[i][1] * inv;
        v.z = o[i][2] * inv; v.w = o[i][3] * inv;
        *(float4*)(Obase + (size_t)(ty * 4 + i) * DM + tx * 4) = v;
    }
}

extern "C" void kernel_launch(void* const* d_in, const int* in_sizes, int n_in,
                              void* d_out, int out_size)
{
    const float* q  = (const float*)d_in[0];
    const float* Wq = (const float*)d_in[1];
    const float* Wk = (const float*)d_in[2];
    const float* Wv = (const float*)d_in[3];
    const float* Wo = (const float*)d_in[4];
    const float* bo = (const float*)d_in[5];

    proj_qkv_kernel<<<dim3(8, 32, 3), 256>>>(q, Wq, Wk, Wv);
    attn_kernel<<<dim3(BATCH * NH, SEQ / 64), 256>>>();
    out_proj_kernel<<<dim3(8, 32), 256>>>(Wo, bo, (float*)d_out);
}

// round 3
// speedup vs baseline: 1.0041x; 1.0041x over previous
#include <cuda_runtime.h>

#define SEQ   2048
#define BATCH 2
#define DM    1024
#define NH    16
#define MTOT  (BATCH*SEQ)   // 4096

// Scratch (static device globals; allocation-guard safe)
__device__ float g_Qb[MTOT * DM];
__device__ float g_Kb[MTOT * DM];
__device__ float g_Vb[MTOT * DM];
__device__ float g_Ctx[MTOT * DM];

// ---------------------------------------------------------------------------
// SGEMM tile: C[m0:m0+128, n0:n0+128] = A[M,1024] @ W[1024,128-slice] * scale (+bias)
// 256 threads, BK=16, 8x8 micro-tile in split-register layout.
// ---------------------------------------------------------------------------
__device__ __forceinline__ void gemm_tile(
    const float* __restrict__ A, const float* __restrict__ W,
    float* __restrict__ C, const float* __restrict__ bias, float scale,
    int m0, int n0, float (&As)[16][132], float (&Bs)[16][128])
{
    const int tid = threadIdx.x;
    const int tx  = tid & 15;
    const int ty  = tid >> 4;

    float acc[8][8];
#pragma unroll
    for (int i = 0; i < 8; i++)
#pragma unroll
        for (int j = 0; j < 8; j++) acc[i][j] = 0.f;

    for (int k0 = 0; k0 < DM; k0 += 16) {
        // A tile: 128 rows x 16 k, stored transposed As[k][m]
#pragma unroll
        for (int e = 0; e < 2; e++) {
            int lin = tid + 256 * e;          // 0..511
            int m   = lin >> 2;
            int k4  = lin & 3;
            float4 v = *(const float4*)(A + (size_t)(m0 + m) * DM + k0 + k4 * 4);
            As[k4 * 4 + 0][m] = v.x;
            As[k4 * 4 + 1][m] = v.y;
            As[k4 * 4 + 2][m] = v.z;
            As[k4 * 4 + 3][m] = v.w;
        }
        // B tile: 16 k x 128 n, natural layout
#pragma unroll
        for (int e = 0; e < 2; e++) {
            int lin = tid + 256 * e;          // 0..511
            int k   = lin >> 5;
            int n4  = lin & 31;
            *(float4*)&Bs[k][n4 * 4] =
                *(const float4*)(W + (size_t)(k0 + k) * DM + n0 + n4 * 4);
        }
        __syncthreads();

#pragma unroll
        for (int kk = 0; kk < 16; kk++) {
            float a[8], b[8];
            *(float4*)&a[0] = *(const float4*)&As[kk][ty * 4];
            *(float4*)&a[4] = *(const float4*)&As[kk][64 + ty * 4];
            *(float4*)&b[0] = *(const float4*)&Bs[kk][tx * 4];
            *(float4*)&b[4] = *(const float4*)&Bs[kk][64 + tx * 4];
#pragma unroll
            for (int i = 0; i < 8; i++)
#pragma unroll
                for (int j = 0; j < 8; j++) acc[i][j] += a[i] * b[j];
        }
        __syncthreads();
    }

#pragma unroll
    for (int i = 0; i < 8; i++) {
        int r = m0 + ((i < 4) ? (ty * 4 + i) : (64 + ty * 4 + (i - 4)));
#pragma unroll
        for (int jh = 0; jh < 2; jh++) {
            int c = n0 + jh * 64 + tx * 4;
            float4 v;
            v.x = acc[i][jh * 4 + 0] * scale;
            v.y = acc[i][jh * 4 + 1] * scale;
            v.z = acc[i][jh * 4 + 2] * scale;
            v.w = acc[i][jh * 4 + 3] * scale;
            if (bias) {
                v.x += bias[c + 0]; v.y += bias[c + 1];
                v.z += bias[c + 2]; v.w += bias[c + 3];
            }
            *(float4*)(C + (size_t)r * DM + c) = v;
        }
    }
}

// QKV projection: z=0 -> Q (scaled by 1/sqrt(64)), z=1 -> K, z=2 -> V
__global__ __launch_bounds__(256, 2)
void proj_qkv_kernel(const float* __restrict__ X, const float* __restrict__ Wq,
                     const float* __restrict__ Wk, const float* __restrict__ Wv)
{
    __shared__ float As[16][132];
    __shared__ float Bs[16][128];
    const float* W; float* C; float scale;
    if (blockIdx.z == 0)      { W = Wq; C = g_Qb; scale = 0.125f; }
    else if (blockIdx.z == 1) { W = Wk; C = g_Kb; scale = 1.0f;  }
    else                      { W = Wv; C = g_Vb; scale = 1.0f;  }
    gemm_tile(X, W, C, nullptr, scale, blockIdx.y * 128, blockIdx.x * 128, As, Bs);
}

// Output projection with bias -> d_out
__global__ __launch_bounds__(256, 2)
void out_proj_kernel(const float* __restrict__ Wo, const float* __restrict__ bo,
                     float* __restrict__ Y)
{
    __shared__ float As[16][132];
    __shared__ float Bs[16][128];
    gemm_tile(g_Ctx, Wo, Y, bo, 1.0f, blockIdx.y * 128, blockIdx.x * 128, As, Bs);
}

// ---------------------------------------------------------------------------
// Flash-style attention, fp32. One block = one (b,h) pair x 64 queries.
// Bk = 32 keys per iteration, online softmax. 256 threads (tx 0..15, ty 0..15).
// Thread owns: S rows 4ty..4ty+3 x cols 2tx..2tx+1; O rows 4ty.. x dcols 4tx..
// ---------------------------------------------------------------------------
__global__ __launch_bounds__(256, 2)
void attn_kernel()
{
    __shared__ float Qt[64][65];   // [d][q], odd stride -> conflict-free scalar
    __shared__ float Kt[64][33];   // [d][k]
    __shared__ float Vs[32][64];   // [k][d], natural, float4-aligned
    __shared__ float Pt[32][68];   // [k][q], stride 68 = 16B aligned for float4 reads

    const int bh = blockIdx.x;            // 0..31
    const int b  = bh >> 4;
    const int h  = bh & 15;
    const int q0 = blockIdx.y * 64;
    const int tid = threadIdx.x;
    const int tx  = tid & 15;
    const int ty  = tid >> 4;

    const float* Qbase = g_Qb + ((size_t)(b * SEQ + q0)) * DM + h * 64;
    const float* Kbase = g_Kb + ((size_t)(b * SEQ)) * DM + h * 64;
    const float* Vbase = g_Vb + ((size_t)(b * SEQ)) * DM + h * 64;

    // Load Q tile transposed: 64 q-rows x 64 d
#pragma unroll
    for (int e = 0; e < 4; e++) {
        int lin = tid + 256 * e;          // 0..1023
        int qq  = lin >> 4;
        int d4  = lin & 15;
        float4 v = *(const float4*)(Qbase + (size_t)qq * DM + d4 * 4);
        Qt[d4 * 4 + 0][qq] = v.x;
        Qt[d4 * 4 + 1][qq] = v.y;
        Qt[d4 * 4 + 2][qq] = v.z;
        Qt[d4 * 4 + 3][qq] = v.w;
    }

    float m_[4], l_[4], o[4][4];
#pragma unroll
    for (int i = 0; i < 4; i++) {
        m_[i] = -1e30f;
        l_[i] = 0.f;
#pragma unroll
        for (int j = 0; j < 4; j++) o[i][j] = 0.f;
    }

    for (int kt = 0; kt < SEQ / 32; kt++) {
        __syncthreads();   // previous PV done before overwriting K/V tiles
        // Load K (transposed) and V (natural) tiles: 32 rows x 64 d each
#pragma unroll
        for (int e = 0; e < 2; e++) {
            int lin = tid + 256 * e;      // 0..511
            int kk  = lin >> 4;
            int d4  = lin & 15;
            float4 v = *(const float4*)(Kbase + (size_t)(kt * 32 + kk) * DM + d4 * 4);
            Kt[d4 * 4 + 0][kk] = v.x;
            Kt[d4 * 4 + 1][kk] = v.y;
            Kt[d4 * 4 + 2][kk] = v.z;
            Kt[d4 * 4 + 3][kk] = v.w;
            float4 w = *(const float4*)(Vbase + (size_t)(kt * 32 + kk) * DM + d4 * 4);
            *(float4*)&Vs[kk][d4 * 4] = w;
        }
        __syncthreads();

        // S = Q K^T  (scale already folded into Q at projection)
        float s[4][2];
#pragma unroll
        for (int i = 0; i < 4; i++) { s[i][0] = 0.f; s[i][1] = 0.f; }
#pragma unroll 16
        for (int d = 0; d < 64; d++) {
            float a0 = Qt[d][ty * 4 + 0];
            float a1 = Qt[d][ty * 4 + 1];
            float a2 = Qt[d][ty * 4 + 2];
            float a3 = Qt[d][ty * 4 + 3];
            float b0 = Kt[d][tx * 2 + 0];
            float b1 = Kt[d][tx * 2 + 1];
            s[0][0] += a0 * b0; s[0][1] += a0 * b1;
            s[1][0] += a1 * b0; s[1][1] += a1 * b1;
            s[2][0] += a2 * b0; s[2][1] += a2 * b1;
            s[3][0] += a3 * b0; s[3][1] += a3 * b1;
        }

        // Online softmax update (row reductions across the 16 tx lanes)
#pragma unroll
        for (int i = 0; i < 4; i++) {
            float mx = fmaxf(s[i][0], s[i][1]);
#pragma unroll
            for (int off = 1; off < 16; off <<= 1)
                mx = fmaxf(mx, __shfl_xor_sync(0xffffffffu, mx, off));
            float nm   = fmaxf(m_[i], mx);
            float corr = __expf(m_[i] - nm);
            float p0   = __expf(s[i][0] - nm);
            float p1   = __expf(s[i][1] - nm);
            float rs   = p0 + p1;
#pragma unroll
            for (int off = 1; off < 16; off <<= 1)
                rs += __shfl_xor_sync(0xffffffffu, rs, off);
            l_[i] = l_[i] * corr + rs;
            m_[i] = nm;
#pragma unroll
            for (int j = 0; j < 4; j++) o[i][j] *= corr;
            Pt[tx * 2 + 0][ty * 4 + i] = p0;
            Pt[tx * 2 + 1][ty * 4 + i] = p1;
        }
        __syncthreads();

        // O += P @ V
#pragma unroll 8
        for (int kk = 0; kk < 32; kk++) {
            float4 a  = *(const float4*)&Pt[kk][ty * 4];
            float4 bb = *(const float4*)&Vs[kk][tx * 4];
            o[0][0] += a.x * bb.x; o[0][1] += a.x * bb.y; o[0][2] += a.x * bb.z; o[0][3] += a.x * bb.w;
            o[1][0] += a.y * bb.x; o[1][1] += a.y * bb.y; o[1][2] += a.y * bb.z; o[1][3] += a.y * bb.w;
            o[2][0] += a.z * bb.x; o[2][1] += a.z * bb.y; o[2][2] += a.z * bb.z; o[2][3] += a.z * bb.w;
            o[3][0] += a.w * bb.x; o[3][1] += a.w * bb.y; o[3][2] += a.w * bb.z; o[3][3] += a.w * bb.w;
        }
    }

    // Normalize and write ctx in [bs, h*64+d] layout (ready for out projection)
    float* Obase = g_Ctx + ((size_t)(b * SEQ + q0)) * DM + h * 64;
#pragma unroll
    for (int i = 0; i < 4; i++) {
        float inv = 1.0f / l_[i];
        float4 v;
        v.x = o[i][0] * inv; v.y = o[i][1] * inv;
        v.z = o[i][2] * inv; v.w = o[i][3] * inv;
        *(float4*)(Obase + (size_t)(ty * 4 + i) * DM + tx * 4) = v;
    }
}

extern "C" void kernel_launch(void* const* d_in, const int* in_sizes, int n_in,
                              void* d_out, int out_size)
{
    const float* q  = (const float*)d_in[0];
    const float* Wq = (const float*)d_in[1];
    const float* Wk = (const float*)d_in[2];
    const float* Wv = (const float*)d_in[3];
    const float* Wo = (const float*)d_in[4];
    const float* bo = (const float*)d_in[5];

    proj_qkv_kernel<<<dim3(8, 32, 3), 256>>>(q, Wq, Wk, Wv);
    attn_kernel<<<dim3(BATCH * NH, SEQ / 64), 256>>>();
    out_proj_kernel<<<dim3(8, 32), 256>>>(Wo, bo, (float*)d_out);
}